// round 3
// baseline (speedup 1.0000x reference)
#include <cuda_runtime.h>
#include <cuda_fp16.h>

#define NMAX 200000
#define EMAX 3200000
#define GMAX 1024

// ---- scratch (static device globals; no runtime allocation) ----
__device__ int     g_cnt[NMAX];
__device__ int     g_rowptr[NMAX + 1];
__device__ int     g_cursor[NMAX];
__device__ int     g_csr[EMAX];
__device__ int     g_bsums[1024];
__device__ int     g_gcnt[GMAX];
__device__ int     g_goff[GMAX];
__device__ float   g_dinv[NMAX];
__device__ float   g_xs9[NMAX * 9];    // dinv * x (layer-1 messages, 9-dim fp32)
__device__ __half2 g_bufh[NMAX * 32];  // layer-2 messages (fp16)
__device__ __half2 g_bufh2[NMAX * 32]; // layer-3 messages (fp16)

// packed fp32x2 FMA (FFMA2 — only reachable via PTX fma.rn.f32x2)
__device__ __forceinline__ unsigned long long ffma2(unsigned long long a,
                                                    unsigned long long b,
                                                    unsigned long long c) {
    unsigned long long d;
    asm("fma.rn.f32x2 %0, %1, %2, %3;" : "=l"(d) : "l"(a), "l"(b), "l"(c));
    return d;
}

// -------------------- setup kernels --------------------

__global__ void k_zero(int n) {
    int i = blockIdx.x * blockDim.x + threadIdx.x;
    if (i < n) g_cnt[i] = 0;
    if (i < GMAX) g_gcnt[i] = 0;
}

__global__ void k_count(const int* __restrict__ dst, const int* __restrict__ batch,
                        int n, int e) {
    int i = blockIdx.x * blockDim.x + threadIdx.x;
    if (i < e) atomicAdd(&g_cnt[dst[i]], 1);
    if (i < n) atomicAdd(&g_gcnt[batch[i]], 1);
}

__global__ void k_scanA(int n) {
    __shared__ int s[1024];
    int t = threadIdx.x;
    int i = blockIdx.x * 1024 + t;
    int v = (i < n) ? g_cnt[i] : 0;
    s[t] = v;
    __syncthreads();
    #pragma unroll
    for (int off = 1; off < 1024; off <<= 1) {
        int u = (t >= off) ? s[t - off] : 0;
        __syncthreads();
        s[t] += u;
        __syncthreads();
    }
    if (i < n) g_rowptr[i] = s[t] - v;
    if (t == 1023) g_bsums[blockIdx.x] = s[1023];
}

__global__ void k_scanB(int nb, int n) {
    __shared__ int s[1024];
    int t = threadIdx.x;
    int v = (t < nb) ? g_bsums[t] : 0;
    s[t] = v;
    __syncthreads();
    #pragma unroll
    for (int off = 1; off < 1024; off <<= 1) {
        int u = (t >= off) ? s[t - off] : 0;
        __syncthreads();
        s[t] += u;
        __syncthreads();
    }
    if (t < nb) g_bsums[t] = s[t] - v;
    if (t == 1023) g_rowptr[n] = s[1023];
}

// finalize rowptr/cursor + dinv + xs9 = dinv * x
__global__ void k_scanC(const float* __restrict__ x, int n) {
    int i = blockIdx.x * blockDim.x + threadIdx.x;
    if (i < n) {
        int r = g_rowptr[i] + g_bsums[i >> 10];
        g_rowptr[i] = r;
        g_cursor[i] = r;
        float dv = rsqrtf((float)(g_cnt[i] + 1));
        g_dinv[i] = dv;
        #pragma unroll
        for (int k = 0; k < 9; k++) g_xs9[i * 9 + k] = dv * x[i * 9 + k];
    }
}

__global__ void k_fill(const int* __restrict__ src, const int* __restrict__ dst, int e) {
    int i = blockIdx.x * blockDim.x + threadIdx.x;
    if (i < e) {
        int d = dst[i];
        int p = atomicAdd(&g_cursor[d], 1);
        g_csr[p] = src[i];
    }
}

__global__ void k_gscan() {
    __shared__ int s[GMAX];
    int t = threadIdx.x;
    int v = g_gcnt[t];
    s[t] = v;
    __syncthreads();
    #pragma unroll
    for (int off = 1; off < GMAX; off <<= 1) {
        int u = (t >= off) ? s[t - off] : 0;
        __syncthreads();
        s[t] += u;
        __syncthreads();
    }
    g_goff[t] = s[t] - v;
}

// -------------------- fused layer kernels --------------------

// fp16 edge gather: accumulate messages of v's in-neighbors into (ax, ay); lane = feat pair
__device__ __forceinline__ void gather_h2(const __half2* __restrict__ buf,
                                          int beg, int end, int lane,
                                          float& ax, float& ay) {
    int e = beg;
    for (; e + 8 <= end; e += 8) {
        int s[8];
        #pragma unroll
        for (int q = 0; q < 8; q++) s[q] = __ldg(&g_csr[e + q]);
        #pragma unroll
        for (int q = 0; q < 8; q++) {
            float2 v = __half22float2(__ldg(&buf[s[q] * 32 + lane]));
            ax += v.x; ay += v.y;
        }
    }
    for (; e < end; e++) {
        int s = __ldg(&g_csr[e]);
        float2 v = __half22float2(__ldg(&buf[s * 32 + lane]));
        ax += v.x; ay += v.y;
    }
}

// shared FFMA2 GEMM mainloop + fp16 epilogue: dst[v] = half(dinv_v * (Z[v] @ W))
__device__ __forceinline__ void gemm_epi_h(const float2* Zs2, const float* __restrict__ W,
                                           __half2* __restrict__ dst,
                                           int base, int n, int tid) {
    int fg = tid & 15, ng = tid >> 4;
    int n0 = ng * 4;
    unsigned long long acc[4][2] = {};
    const unsigned long long* Wq = reinterpret_cast<const unsigned long long*>(W);
    #pragma unroll 4
    for (int k = 0; k < 64; k++) {
        unsigned long long w01 = __ldg(&Wq[k * 32 + fg * 2]);
        unsigned long long w23 = __ldg(&Wq[k * 32 + fg * 2 + 1]);
        #pragma unroll
        for (int j = 0; j < 4; j++) {
            unsigned long long z =
                *reinterpret_cast<const unsigned long long*>(&Zs2[(n0 + j) * 64 + k]);
            acc[j][0] = ffma2(z, w01, acc[j][0]);
            acc[j][1] = ffma2(z, w23, acc[j][1]);
        }
    }
    #pragma unroll
    for (int j = 0; j < 4; j++) {
        int v = base + n0 + j;
        if (v < n) {
            float dv = g_dinv[v];
            float2 a0 = *reinterpret_cast<float2*>(&acc[j][0]);
            float2 a1 = *reinterpret_cast<float2*>(&acc[j][1]);
            __half2 h0 = __floats2half2_rn(dv * a0.x, dv * a0.y);
            __half2 h1 = __floats2half2_rn(dv * a1.x, dv * a1.y);
            uint2 u;
            u.x = *reinterpret_cast<unsigned*>(&h0);
            u.y = *reinterpret_cast<unsigned*>(&h1);
            *reinterpret_cast<uint2*>(&dst[v * 32 + fg * 2]) = u;
        }
    }
}

// layer 1 fused: gather xs9 -> agg9 -> h1 = relu(dinv*(agg9@W1)+b1) -> bufh = half(dinv*(h1@W2))
__global__ __launch_bounds__(256) void k_L1f(const float* __restrict__ W1,
                                             const float* __restrict__ b1,
                                             const float* __restrict__ W2, int n) {
    __shared__ float W1s[9 * 64];
    __shared__ float A9s[64 * 9];
    __shared__ float dvs[64];
    __shared__ float b1s[64];
    __shared__ float2 Zs2[64 * 64];
    int tid = threadIdx.x, lane = tid & 31, wid = tid >> 5;
    int base = blockIdx.x * 64;
    for (int i = tid; i < 576; i += 256) W1s[i] = W1[i];
    if (tid < 64) {
        int v = base + tid;
        dvs[tid] = (v < n) ? g_dinv[v] : 0.f;
        b1s[tid] = b1[tid];
    }
    // gather phase: warp wid handles nodes wid*8 .. wid*8+7
    bool act = lane < 9;
    #pragma unroll
    for (int j = 0; j < 8; j++) {
        int nl = wid * 8 + j, v = base + nl;
        float acc = 0.f;
        if (v < n) {
            int eb = g_rowptr[v], ee = g_rowptr[v + 1];
            acc = act ? g_xs9[v * 9 + lane] : 0.f;
            int e = eb;
            for (; e + 8 <= ee; e += 8) {
                int s[8];
                #pragma unroll
                for (int q = 0; q < 8; q++) s[q] = __ldg(&g_csr[e + q]);
                if (act) {
                    #pragma unroll
                    for (int q = 0; q < 8; q++) acc += g_xs9[s[q] * 9 + lane];
                }
            }
            for (; e < ee; e++) {
                int s = __ldg(&g_csr[e]);
                if (act) acc += g_xs9[s * 9 + lane];
            }
        }
        if (act) A9s[nl * 9 + lane] = acc;
    }
    __syncthreads();
    // h1 = relu(dinv * (A9 @ W1) + b1), duplicated into Zs2
    for (int i = tid; i < 4096; i += 256) {
        int nl = i >> 6, f = i & 63;
        float s = 0.f;
        #pragma unroll
        for (int k = 0; k < 9; k++) s = fmaf(A9s[nl * 9 + k], W1s[k * 64 + f], s);
        float z = fmaxf(fmaf(dvs[nl], s, b1s[f]), 0.f);
        Zs2[nl * 64 + f] = make_float2(z, z);
    }
    __syncthreads();
    gemm_epi_h(Zs2, W2, g_bufh, base, n, tid);
}

// layer 2 fused: gather bufh -> h2 = relu(dinv*S2+b2) -> bufh2 = half(dinv*(h2@W3))
__global__ __launch_bounds__(256) void k_L2f(const float* __restrict__ W3,
                                             const float* __restrict__ b2, int n) {
    __shared__ float2 Zs2[64 * 64];
    __shared__ float dvs[64];
    __shared__ float bs[64];
    int tid = threadIdx.x, lane = tid & 31, wid = tid >> 5;
    int base = blockIdx.x * 64;
    if (tid < 64) {
        int v = base + tid;
        dvs[tid] = (v < n) ? g_dinv[v] : 0.f;
        bs[tid] = b2[tid];
    }
    __syncthreads();
    int f0 = lane * 2;
    #pragma unroll
    for (int j = 0; j < 8; j++) {
        int nl = wid * 8 + j, v = base + nl;
        float ax = 0.f, ay = 0.f;
        if (v < n) {
            int eb = g_rowptr[v], ee = g_rowptr[v + 1];
            float2 hs = __half22float2(g_bufh[v * 32 + lane]);  // self-loop
            ax = hs.x; ay = hs.y;
            gather_h2(g_bufh, eb, ee, lane, ax, ay);
        }
        float zx = fmaxf(fmaf(dvs[nl], ax, bs[f0]), 0.f);
        float zy = fmaxf(fmaf(dvs[nl], ay, bs[f0 + 1]), 0.f);
        Zs2[nl * 64 + f0]     = make_float2(zx, zx);
        Zs2[nl * 64 + f0 + 1] = make_float2(zy, zy);
    }
    __syncthreads();
    gemm_epi_h(Zs2, W3, g_bufh2, base, n, tid);
}

// pooling fused: per graph, gather bufh2 -> h3 = relu(dinv*S3+b3) -> mean/max -> head
__global__ __launch_bounds__(512) void k_poolf(const float* __restrict__ b3,
                                               const float* __restrict__ Wl,
                                               const float* __restrict__ bl,
                                               float* __restrict__ outp) {
    __shared__ float ssum[16][64];
    __shared__ float smax[16][64];
    __shared__ float pooled[128];
    int g = blockIdx.x, tid = threadIdx.x, lane = tid & 31, wid = tid >> 5;
    int beg = g_goff[g], cnt = g_gcnt[g];
    int f0 = lane * 2;
    float bx = b3[f0], by = b3[f0 + 1];
    float sx = 0.f, sy = 0.f, mx = 0.f, my = 0.f;   // relu>=0 -> 0 is valid max identity
    for (int i = wid; i < cnt; i += 16) {
        int v = beg + i;
        int eb = g_rowptr[v], ee = g_rowptr[v + 1];
        float2 hs = __half22float2(g_bufh2[v * 32 + lane]);
        float ax = hs.x, ay = hs.y;
        gather_h2(g_bufh2, eb, ee, lane, ax, ay);
        float dv = g_dinv[v];
        float hx = fmaxf(fmaf(dv, ax, bx), 0.f);
        float hy = fmaxf(fmaf(dv, ay, by), 0.f);
        sx += hx; sy += hy;
        mx = fmaxf(mx, hx); my = fmaxf(my, hy);
    }
    ssum[wid][f0] = sx; ssum[wid][f0 + 1] = sy;
    smax[wid][f0] = mx; smax[wid][f0 + 1] = my;
    __syncthreads();
    if (tid < 64) {
        float s = 0.f, m = 0.f;
        #pragma unroll
        for (int w = 0; w < 16; w++) {
            s += ssum[w][tid];
            m = fmaxf(m, smax[w][tid]);
        }
        pooled[tid] = s / fmaxf((float)cnt, 1.f);
        pooled[64 + tid] = m;
    }
    __syncthreads();
    if (tid < 64) {
        float o = bl[tid];
        #pragma unroll 8
        for (int k = 0; k < 128; k++) o = fmaf(pooled[k], Wl[k * 64 + tid], o);
        outp[g * 64 + tid] = o;
    }
}

// -------------------- launcher --------------------

extern "C" void kernel_launch(void* const* d_in, const int* in_sizes, int n_in,
                              void* d_out, int out_size) {
    const float* x     = (const float*)d_in[0];
    const int*   ei    = (const int*)  d_in[1];
    const int*   batch = (const int*)  d_in[3];
    const float* W1    = (const float*)d_in[4];
    const float* b1    = (const float*)d_in[5];
    const float* W2    = (const float*)d_in[6];
    const float* b2    = (const float*)d_in[7];
    const float* W3    = (const float*)d_in[8];
    const float* b3    = (const float*)d_in[9];
    const float* Wl    = (const float*)d_in[10];
    const float* bl    = (const float*)d_in[11];
    float* out = (float*)d_out;

    int n = in_sizes[0] / 9;
    int e = in_sizes[1] / 2;
    const int* src = ei;
    const int* dst = ei + e;

    int gn = (n + 255) / 256;
    int ge = (e + 255) / 256;
    int nb = (n + 1023) / 1024;

    // graph structure
    k_zero<<<gn, 256>>>(n);
    k_count<<<ge, 256>>>(dst, batch, n, e);
    k_scanA<<<nb, 1024>>>(n);
    k_scanB<<<1, 1024>>>(nb, n);
    k_scanC<<<gn, 256>>>(x, n);
    k_fill<<<ge, 256>>>(src, dst, e);
    k_gscan<<<1, GMAX>>>();

    // fused layers
    k_L1f<<<(n + 63) / 64, 256>>>(W1, b1, W2, n);
    k_L2f<<<(n + 63) / 64, 256>>>(W3, b2, n);
    k_poolf<<<GMAX, 512>>>(b3, Wl, bl, out);
}

// round 4
// speedup vs baseline: 1.1686x; 1.1686x over previous
#include <cuda_runtime.h>
#include <cuda_fp16.h>

#define NMAX 200000
#define EMAX 3200000
#define GMAX 1024

// ---- scratch (static device globals; no runtime allocation) ----
__device__ int     g_cnt[NMAX];
__device__ int     g_rowptr[NMAX + 1];
__device__ int     g_cursor[NMAX];
__device__ int     g_csr[EMAX];
__device__ int     g_bsums[1024];
__device__ int     g_gcnt[GMAX];
__device__ int     g_goff[GMAX];
__device__ float   g_dinv[NMAX];
__device__ float   g_xs9[NMAX * 9];    // dinv * x (layer-1 messages)
__device__ float   g_agg9[NMAX * 9];   // layer-1 aggregated sums
__device__ __half2 g_bufh[NMAX * 32];  // fp16 messages
__device__ float   g_bufa[NMAX * 64];  // fp32 aggregated sums

// packed fp32x2 FMA (FFMA2 — only reachable via PTX fma.rn.f32x2)
__device__ __forceinline__ unsigned long long ffma2(unsigned long long a,
                                                    unsigned long long b,
                                                    unsigned long long c) {
    unsigned long long d;
    asm("fma.rn.f32x2 %0, %1, %2, %3;" : "=l"(d) : "l"(a), "l"(b), "l"(c));
    return d;
}

// -------------------- setup kernels --------------------

__global__ void k_zero(int n) {
    int i = blockIdx.x * blockDim.x + threadIdx.x;
    if (i < n) g_cnt[i] = 0;
    if (i < GMAX) g_gcnt[i] = 0;
}

// 4 edges per thread via int4
__global__ void k_count(const int* __restrict__ dst, const int* __restrict__ batch,
                        int n, int e) {
    int i = blockIdx.x * blockDim.x + threadIdx.x;
    int e4 = i * 4;
    if (e4 + 4 <= e) {
        int4 d = *reinterpret_cast<const int4*>(&dst[e4]);
        atomicAdd(&g_cnt[d.x], 1);
        atomicAdd(&g_cnt[d.y], 1);
        atomicAdd(&g_cnt[d.z], 1);
        atomicAdd(&g_cnt[d.w], 1);
    } else {
        for (int q = e4; q < e; q++) atomicAdd(&g_cnt[dst[q]], 1);
    }
    int n4 = i * 4;
    if (n4 + 4 <= n) {
        int4 b = *reinterpret_cast<const int4*>(&batch[n4]);
        atomicAdd(&g_gcnt[b.x], 1);
        atomicAdd(&g_gcnt[b.y], 1);
        atomicAdd(&g_gcnt[b.z], 1);
        atomicAdd(&g_gcnt[b.w], 1);
    } else {
        for (int q = n4; q < n; q++) atomicAdd(&g_gcnt[batch[q]], 1);
    }
}

__global__ void k_scanA(int n) {
    __shared__ int s[1024];
    int t = threadIdx.x;
    int i = blockIdx.x * 1024 + t;
    int v = (i < n) ? g_cnt[i] : 0;
    s[t] = v;
    __syncthreads();
    #pragma unroll
    for (int off = 1; off < 1024; off <<= 1) {
        int u = (t >= off) ? s[t - off] : 0;
        __syncthreads();
        s[t] += u;
        __syncthreads();
    }
    if (i < n) g_rowptr[i] = s[t] - v;
    if (t == 1023) g_bsums[blockIdx.x] = s[1023];
}

__global__ void k_scanB(int nb, int n) {
    __shared__ int s[1024];
    int t = threadIdx.x;
    int v = (t < nb) ? g_bsums[t] : 0;
    s[t] = v;
    __syncthreads();
    #pragma unroll
    for (int off = 1; off < 1024; off <<= 1) {
        int u = (t >= off) ? s[t - off] : 0;
        __syncthreads();
        s[t] += u;
        __syncthreads();
    }
    if (t < nb) g_bsums[t] = s[t] - v;
    if (t == 1023) g_rowptr[n] = s[1023];
}

__global__ void k_scanC(const float* __restrict__ x, int n) {
    int i = blockIdx.x * blockDim.x + threadIdx.x;
    if (i < n) {
        int r = g_rowptr[i] + g_bsums[i >> 10];
        g_rowptr[i] = r;
        g_cursor[i] = r;
        float dv = rsqrtf((float)(g_cnt[i] + 1));
        g_dinv[i] = dv;
        #pragma unroll
        for (int k = 0; k < 9; k++) g_xs9[i * 9 + k] = dv * x[i * 9 + k];
    }
}

// 4 edges per thread via int4
__global__ void k_fill(const int* __restrict__ src, const int* __restrict__ dst, int e) {
    int i = blockIdx.x * blockDim.x + threadIdx.x;
    int e4 = i * 4;
    if (e4 + 4 <= e) {
        int4 d = *reinterpret_cast<const int4*>(&dst[e4]);
        int4 s = *reinterpret_cast<const int4*>(&src[e4]);
        g_csr[atomicAdd(&g_cursor[d.x], 1)] = s.x;
        g_csr[atomicAdd(&g_cursor[d.y], 1)] = s.y;
        g_csr[atomicAdd(&g_cursor[d.z], 1)] = s.z;
        g_csr[atomicAdd(&g_cursor[d.w], 1)] = s.w;
    } else {
        for (int q = e4; q < e; q++)
            g_csr[atomicAdd(&g_cursor[dst[q]], 1)] = src[q];
    }
}

__global__ void k_gscan() {
    __shared__ int s[GMAX];
    int t = threadIdx.x;
    int v = g_gcnt[t];
    s[t] = v;
    __syncthreads();
    #pragma unroll
    for (int off = 1; off < GMAX; off <<= 1) {
        int u = (t >= off) ? s[t - off] : 0;
        __syncthreads();
        s[t] += u;
        __syncthreads();
    }
    g_goff[t] = s[t] - v;
}

// -------------------- layer kernels --------------------

// layer-1 aggregation: 2 nodes per warp (16 lanes each, lanes 0-8 active)
__global__ __launch_bounds__(256) void k_gather9(int n) {
    int gw = (blockIdx.x * blockDim.x + threadIdx.x) >> 5;
    int lane = threadIdx.x & 31;
    int half = lane >> 4, hl = lane & 15;
    int v = gw * 2 + half;
    if (v >= n) return;
    int beg = g_rowptr[v], end = g_rowptr[v + 1];
    bool act = hl < 9;
    float acc = act ? g_xs9[v * 9 + hl] : 0.f;
    int e = beg;
    for (; e + 8 <= end; e += 8) {
        int s[8];
        #pragma unroll
        for (int q = 0; q < 8; q++) s[q] = __ldg(&g_csr[e + q]);
        if (act) {
            #pragma unroll
            for (int q = 0; q < 8; q++) acc += g_xs9[s[q] * 9 + hl];
        }
    }
    for (; e < end; e++) {
        int s = __ldg(&g_csr[e]);
        if (act) acc += g_xs9[s * 9 + hl];
    }
    if (act) g_agg9[v * 9 + hl] = acc;
}

// fp16 aggregation: 2 nodes per warp; each lane covers 4 feats via uint2
__global__ __launch_bounds__(256) void k_gather_h(int n) {
    int gw = (blockIdx.x * blockDim.x + threadIdx.x) >> 5;
    int lane = threadIdx.x & 31;
    int half = lane >> 4, hl = lane & 15;
    int v = gw * 2 + half;
    if (v >= n) return;
    int beg = g_rowptr[v], end = g_rowptr[v + 1];
    const uint2* buf = reinterpret_cast<const uint2*>(g_bufh);  // 16 uint2 per row
    uint2 u = __ldg(&buf[v * 16 + hl]);   // self-loop
    float2 p0 = __half22float2(*reinterpret_cast<__half2*>(&u.x));
    float2 p1 = __half22float2(*reinterpret_cast<__half2*>(&u.y));
    float a0 = p0.x, a1 = p0.y, a2 = p1.x, a3 = p1.y;
    int e = beg;
    for (; e + 8 <= end; e += 8) {
        int s[8];
        #pragma unroll
        for (int q = 0; q < 8; q++) s[q] = __ldg(&g_csr[e + q]);
        #pragma unroll
        for (int q = 0; q < 8; q++) {
            uint2 w = __ldg(&buf[s[q] * 16 + hl]);
            float2 q0 = __half22float2(*reinterpret_cast<__half2*>(&w.x));
            float2 q1 = __half22float2(*reinterpret_cast<__half2*>(&w.y));
            a0 += q0.x; a1 += q0.y; a2 += q1.x; a3 += q1.y;
        }
    }
    for (; e < end; e++) {
        int s = __ldg(&g_csr[e]);
        uint2 w = __ldg(&buf[s * 16 + hl]);
        float2 q0 = __half22float2(*reinterpret_cast<__half2*>(&w.x));
        float2 q1 = __half22float2(*reinterpret_cast<__half2*>(&w.y));
        a0 += q0.x; a1 += q0.y; a2 += q1.x; a3 += q1.y;
    }
    *reinterpret_cast<float4*>(&g_bufa[v * 64 + hl * 4]) = make_float4(a0, a1, a2, a3);
}

// shared FFMA2 GEMM mainloop + fp16 epilogue: dst[v] = half(dinv_v * (Z[v] @ W))
__device__ __forceinline__ void gemm_epi_h(const float2* Zs2, const float* __restrict__ W,
                                           __half2* __restrict__ dst,
                                           int base, int n, int tid) {
    int fg = tid & 15, ng = tid >> 4;
    int n0 = ng * 4;
    unsigned long long acc[4][2] = {};
    const unsigned long long* Wq = reinterpret_cast<const unsigned long long*>(W);
    #pragma unroll 4
    for (int k = 0; k < 64; k++) {
        unsigned long long w01 = __ldg(&Wq[k * 32 + fg * 2]);
        unsigned long long w23 = __ldg(&Wq[k * 32 + fg * 2 + 1]);
        #pragma unroll
        for (int j = 0; j < 4; j++) {
            unsigned long long z =
                *reinterpret_cast<const unsigned long long*>(&Zs2[(n0 + j) * 64 + k]);
            acc[j][0] = ffma2(z, w01, acc[j][0]);
            acc[j][1] = ffma2(z, w23, acc[j][1]);
        }
    }
    #pragma unroll
    for (int j = 0; j < 4; j++) {
        int v = base + n0 + j;
        if (v < n) {
            float dv = g_dinv[v];
            float2 a0 = *reinterpret_cast<float2*>(&acc[j][0]);
            float2 a1 = *reinterpret_cast<float2*>(&acc[j][1]);
            __half2 h0 = __floats2half2_rn(dv * a0.x, dv * a0.y);
            __half2 h1 = __floats2half2_rn(dv * a1.x, dv * a1.y);
            uint2 u;
            u.x = *reinterpret_cast<unsigned*>(&h0);
            u.y = *reinterpret_cast<unsigned*>(&h1);
            *reinterpret_cast<uint2*>(&dst[v * 32 + fg * 2]) = u;
        }
    }
}

// layer 1: z = relu(dinv*(agg9 @ W1) + b1); bufh = half(dinv * (z @ W2))
__global__ __launch_bounds__(256) void k_l1(const float* __restrict__ W1,
                                            const float* __restrict__ b1,
                                            const float* __restrict__ W2, int n) {
    __shared__ float W1s[9 * 64];
    __shared__ float A9s[64 * 9];
    __shared__ float dvs[64];
    __shared__ float b1s[64];
    __shared__ float2 Zs2[64 * 64];
    int tid = threadIdx.x;
    int base = blockIdx.x * 64;
    for (int i = tid; i < 576; i += 256) W1s[i] = W1[i];
    if (tid < 64) {
        int v = base + tid;
        dvs[tid] = (v < n) ? g_dinv[v] : 0.f;
        b1s[tid] = b1[tid];
    }
    for (int i = tid; i < 576; i += 256) {
        int nl = i / 9, k = i - nl * 9;
        int v = base + nl;
        A9s[i] = (v < n) ? g_agg9[v * 9 + k] : 0.f;
    }
    __syncthreads();
    for (int i = tid; i < 4096; i += 256) {
        int nl = i >> 6, f = i & 63;
        float s = 0.f;
        #pragma unroll
        for (int k = 0; k < 9; k++) s = fmaf(A9s[nl * 9 + k], W1s[k * 64 + f], s);
        float z = fmaxf(fmaf(dvs[nl], s, b1s[f]), 0.f);
        Zs2[nl * 64 + f] = make_float2(z, z);
    }
    __syncthreads();
    gemm_epi_h(Zs2, W2, g_bufh, base, n, tid);
}

// middle layer: z = relu(dinv*bufa + bias); bufh = half(dinv * (z @ W))
__global__ __launch_bounds__(256) void k_tf(const float* __restrict__ W,
                                            const float* __restrict__ bias, int n) {
    __shared__ float2 Zs2[64 * 64];
    __shared__ float b_s[64];
    __shared__ float dvs[64];
    int tid = threadIdx.x;
    int base = blockIdx.x * 64;
    if (tid < 64) {
        b_s[tid] = bias[tid];
        int v = base + tid;
        dvs[tid] = (v < n) ? g_dinv[v] : 0.f;
    }
    __syncthreads();
    for (int i = tid; i < 4096; i += 256) {
        int nl = i >> 6, f = i & 63;
        int v = base + nl;
        float z = 0.f;
        if (v < n) z = fmaxf(fmaf(dvs[nl], g_bufa[v * 64 + f], b_s[f]), 0.f);
        Zs2[nl * 64 + f] = make_float2(z, z);
    }
    __syncthreads();
    gemm_epi_h(Zs2, W, g_bufh, base, n, tid);
}

// pooling + head: 256 threads per graph (4 warps stride the nodes)
__global__ __launch_bounds__(256) void k_pool(const float* __restrict__ b3,
                                              const float* __restrict__ Wl,
                                              const float* __restrict__ bl,
                                              float* __restrict__ outp) {
    __shared__ float ssum[4][64];
    __shared__ float smax[4][64];
    __shared__ float pooled[128];
    int g = blockIdx.x, tid = threadIdx.x;
    int f = tid & 63, part = tid >> 6;
    int beg = g_goff[g], cnt = g_gcnt[g];
    float bf = b3[f];
    float sum = 0.f, mx = 0.f;   // relu>=0 -> 0 valid for max identity
    for (int i = part; i < cnt; i += 4) {
        int v = beg + i;
        float val = fmaxf(fmaf(g_dinv[v], g_bufa[v * 64 + f], bf), 0.f);
        sum += val;
        mx = fmaxf(mx, val);
    }
    ssum[part][f] = sum;
    smax[part][f] = mx;
    __syncthreads();
    if (tid < 64) {
        float s = 0.f, m = 0.f;
        #pragma unroll
        for (int w = 0; w < 4; w++) {
            s += ssum[w][tid];
            m = fmaxf(m, smax[w][tid]);
        }
        pooled[tid] = s / fmaxf((float)cnt, 1.f);
        pooled[64 + tid] = m;
    }
    __syncthreads();
    if (tid < 64) {
        float o = bl[tid];
        #pragma unroll 8
        for (int k = 0; k < 128; k++) o = fmaf(pooled[k], Wl[k * 64 + tid], o);
        outp[g * 64 + tid] = o;
    }
}

// -------------------- launcher --------------------

extern "C" void kernel_launch(void* const* d_in, const int* in_sizes, int n_in,
                              void* d_out, int out_size) {
    const float* x     = (const float*)d_in[0];
    const int*   ei    = (const int*)  d_in[1];
    const int*   batch = (const int*)  d_in[3];
    const float* W1    = (const float*)d_in[4];
    const float* b1    = (const float*)d_in[5];
    const float* W2    = (const float*)d_in[6];
    const float* b2    = (const float*)d_in[7];
    const float* W3    = (const float*)d_in[8];
    const float* b3    = (const float*)d_in[9];
    const float* Wl    = (const float*)d_in[10];
    const float* bl    = (const float*)d_in[11];
    float* out = (float*)d_out;

    int n = in_sizes[0] / 9;
    int e = in_sizes[1] / 2;
    const int* src = ei;
    const int* dst = ei + e;

    int gn  = (n + 255) / 256;
    int nb  = (n + 1023) / 1024;
    int ge4 = (e / 4 + 255) / 256 + 1;
    int gw2 = ((n + 1) / 2 * 32 + 255) / 256;   // 2 nodes per warp

    // graph structure
    k_zero<<<gn, 256>>>(n);
    k_count<<<ge4, 256>>>(dst, batch, n, e);
    k_scanA<<<nb, 1024>>>(n);
    k_scanB<<<1, 1024>>>(nb, n);
    k_scanC<<<gn, 256>>>(x, n);
    k_fill<<<ge4, 256>>>(src, dst, e);
    k_gscan<<<1, GMAX>>>();

    // layer 1
    k_gather9<<<gw2, 256>>>(n);
    k_l1<<<(n + 63) / 64, 256>>>(W1, b1, W2, n);
    // layer 2
    k_gather_h<<<gw2, 256>>>(n);
    k_tf<<<(n + 63) / 64, 256>>>(W3, b2, n);
    // layer 3
    k_gather_h<<<gw2, 256>>>(n);
    // pooling + head
    k_pool<<<GMAX, 256>>>(b3, Wl, bl, out);
}

// round 5
// speedup vs baseline: 1.2147x; 1.0395x over previous
#include <cuda_runtime.h>
#include <cuda_fp16.h>

#define NMAX 200000
#define EMAX 3200000
#define GMAX 1024

// ---- scratch (static device globals; no runtime allocation) ----
__device__ int     g_cnt[NMAX];
__device__ int     g_rowptr[NMAX + 1];
__device__ int     g_rank[EMAX];       // edge rank within its dst row
__device__ int     g_csr[EMAX];
__device__ int     g_bsums[1024];
__device__ int     g_gcnt[GMAX];
__device__ int     g_goff[GMAX];
__device__ float   g_dinv[NMAX];
__device__ float   g_xs9[NMAX * 9];    // dinv * x (layer-1 messages)
__device__ float   g_agg9[NMAX * 9];   // layer-1 aggregated sums
__device__ __half2 g_bufh[NMAX * 32];  // fp16 messages
__device__ float   g_bufa[NMAX * 64];  // fp32 aggregated sums

// packed fp32x2 FMA (FFMA2 — only reachable via PTX fma.rn.f32x2)
__device__ __forceinline__ unsigned long long ffma2(unsigned long long a,
                                                    unsigned long long b,
                                                    unsigned long long c) {
    unsigned long long d;
    asm("fma.rn.f32x2 %0, %1, %2, %3;" : "=l"(d) : "l"(a), "l"(b), "l"(c));
    return d;
}

// -------------------- setup kernels --------------------

__global__ void k_zero(int n) {
    int i = blockIdx.x * blockDim.x + threadIdx.x;
    if (i < n) g_cnt[i] = 0;
    if (i < GMAX) g_gcnt[i] = 0;
}

// 4 edges per thread; atomic returns rank within row (stored for rank-based fill)
__global__ void k_count(const int* __restrict__ dst, const int* __restrict__ batch,
                        int n, int e) {
    int i = blockIdx.x * blockDim.x + threadIdx.x;
    int e4 = i * 4;
    if (e4 + 4 <= e) {
        int4 d = *reinterpret_cast<const int4*>(&dst[e4]);
        int4 r;
        r.x = atomicAdd(&g_cnt[d.x], 1);
        r.y = atomicAdd(&g_cnt[d.y], 1);
        r.z = atomicAdd(&g_cnt[d.z], 1);
        r.w = atomicAdd(&g_cnt[d.w], 1);
        *reinterpret_cast<int4*>(&g_rank[e4]) = r;
    } else {
        for (int q = e4; q < e; q++) g_rank[q] = atomicAdd(&g_cnt[dst[q]], 1);
    }
    int n4 = i * 4;
    if (n4 + 4 <= n) {
        int4 b = *reinterpret_cast<const int4*>(&batch[n4]);
        atomicAdd(&g_gcnt[b.x], 1);
        atomicAdd(&g_gcnt[b.y], 1);
        atomicAdd(&g_gcnt[b.z], 1);
        atomicAdd(&g_gcnt[b.w], 1);
    } else {
        for (int q = n4; q < n; q++) atomicAdd(&g_gcnt[batch[q]], 1);
    }
}

__global__ void k_scanA(int n) {
    __shared__ int s[1024];
    int t = threadIdx.x;
    int i = blockIdx.x * 1024 + t;
    int v = (i < n) ? g_cnt[i] : 0;
    s[t] = v;
    __syncthreads();
    #pragma unroll
    for (int off = 1; off < 1024; off <<= 1) {
        int u = (t >= off) ? s[t - off] : 0;
        __syncthreads();
        s[t] += u;
        __syncthreads();
    }
    if (i < n) g_rowptr[i] = s[t] - v;
    if (t == 1023) g_bsums[blockIdx.x] = s[1023];
}

__global__ void k_scanB(int nb, int n) {
    __shared__ int s[1024];
    int t = threadIdx.x;
    int v = (t < nb) ? g_bsums[t] : 0;
    s[t] = v;
    __syncthreads();
    #pragma unroll
    for (int off = 1; off < 1024; off <<= 1) {
        int u = (t >= off) ? s[t - off] : 0;
        __syncthreads();
        s[t] += u;
        __syncthreads();
    }
    if (t < nb) g_bsums[t] = s[t] - v;
    if (t == 1023) g_rowptr[n] = s[1023];
}

__global__ void k_scanC(const float* __restrict__ x, int n) {
    int i = blockIdx.x * blockDim.x + threadIdx.x;
    if (i < n) {
        g_rowptr[i] += g_bsums[i >> 10];
        float dv = rsqrtf((float)(g_cnt[i] + 1));
        g_dinv[i] = dv;
        #pragma unroll
        for (int k = 0; k < 9; k++) g_xs9[i * 9 + k] = dv * x[i * 9 + k];
    }
}

// rank-based fill: no atomics, plain gather of rowptr + scatter write
__global__ void k_fill(const int* __restrict__ src, const int* __restrict__ dst, int e) {
    int i = blockIdx.x * blockDim.x + threadIdx.x;
    int e4 = i * 4;
    if (e4 + 4 <= e) {
        int4 d = *reinterpret_cast<const int4*>(&dst[e4]);
        int4 s = *reinterpret_cast<const int4*>(&src[e4]);
        int4 r = *reinterpret_cast<const int4*>(&g_rank[e4]);
        g_csr[__ldg(&g_rowptr[d.x]) + r.x] = s.x;
        g_csr[__ldg(&g_rowptr[d.y]) + r.y] = s.y;
        g_csr[__ldg(&g_rowptr[d.z]) + r.z] = s.z;
        g_csr[__ldg(&g_rowptr[d.w]) + r.w] = s.w;
    } else {
        for (int q = e4; q < e; q++)
            g_csr[__ldg(&g_rowptr[dst[q]]) + g_rank[q]] = src[q];
    }
}

__global__ void k_gscan() {
    __shared__ int s[GMAX];
    int t = threadIdx.x;
    int v = g_gcnt[t];
    s[t] = v;
    __syncthreads();
    #pragma unroll
    for (int off = 1; off < GMAX; off <<= 1) {
        int u = (t >= off) ? s[t - off] : 0;
        __syncthreads();
        s[t] += u;
        __syncthreads();
    }
    g_goff[t] = s[t] - v;
}

// -------------------- layer kernels --------------------

// layer-1 aggregation: 2 nodes per warp (16 lanes each, lanes 0-8 active)
__global__ __launch_bounds__(256) void k_gather9(int n) {
    int gw = (blockIdx.x * blockDim.x + threadIdx.x) >> 5;
    int lane = threadIdx.x & 31;
    int half = lane >> 4, hl = lane & 15;
    int v = gw * 2 + half;
    if (v >= n) return;
    int beg = g_rowptr[v], end = g_rowptr[v + 1];
    bool act = hl < 9;
    float acc = act ? g_xs9[v * 9 + hl] : 0.f;
    int e = beg;
    for (; e + 8 <= end; e += 8) {
        int s[8];
        #pragma unroll
        for (int q = 0; q < 8; q++) s[q] = __ldg(&g_csr[e + q]);
        if (act) {
            #pragma unroll
            for (int q = 0; q < 8; q++) acc += g_xs9[s[q] * 9 + hl];
        }
    }
    for (; e < end; e++) {
        int s = __ldg(&g_csr[e]);
        if (act) acc += g_xs9[s * 9 + hl];
    }
    if (act) g_agg9[v * 9 + hl] = acc;
}

// fp16 aggregation: 4 nodes per warp; 8 lanes per node, each lane covers 8 feats (uint4)
__global__ __launch_bounds__(256) void k_gather_h(int n) {
    int gw = (blockIdx.x * blockDim.x + threadIdx.x) >> 5;
    int lane = threadIdx.x & 31;
    int quad = lane >> 3, ql = lane & 7;
    int v = gw * 4 + quad;
    if (v >= n) return;
    int beg = g_rowptr[v], end = g_rowptr[v + 1];
    const uint4* buf = reinterpret_cast<const uint4*>(g_bufh);  // 8 uint4 per 128B row
    uint4 u = __ldg(&buf[v * 8 + ql]);   // self-loop
    float2 p0 = __half22float2(*reinterpret_cast<__half2*>(&u.x));
    float2 p1 = __half22float2(*reinterpret_cast<__half2*>(&u.y));
    float2 p2 = __half22float2(*reinterpret_cast<__half2*>(&u.z));
    float2 p3 = __half22float2(*reinterpret_cast<__half2*>(&u.w));
    float a0 = p0.x, a1 = p0.y, a2 = p1.x, a3 = p1.y;
    float a4 = p2.x, a5 = p2.y, a6 = p3.x, a7 = p3.y;
    int e = beg;
    for (; e + 8 <= end; e += 8) {
        int s[8];
        #pragma unroll
        for (int q = 0; q < 8; q++) s[q] = __ldg(&g_csr[e + q]);
        #pragma unroll
        for (int q = 0; q < 8; q++) {
            uint4 w = __ldg(&buf[s[q] * 8 + ql]);
            float2 q0 = __half22float2(*reinterpret_cast<__half2*>(&w.x));
            float2 q1 = __half22float2(*reinterpret_cast<__half2*>(&w.y));
            float2 q2 = __half22float2(*reinterpret_cast<__half2*>(&w.z));
            float2 q3 = __half22float2(*reinterpret_cast<__half2*>(&w.w));
            a0 += q0.x; a1 += q0.y; a2 += q1.x; a3 += q1.y;
            a4 += q2.x; a5 += q2.y; a6 += q3.x; a7 += q3.y;
        }
    }
    for (; e < end; e++) {
        int s = __ldg(&g_csr[e]);
        uint4 w = __ldg(&buf[s * 8 + ql]);
        float2 q0 = __half22float2(*reinterpret_cast<__half2*>(&w.x));
        float2 q1 = __half22float2(*reinterpret_cast<__half2*>(&w.y));
        float2 q2 = __half22float2(*reinterpret_cast<__half2*>(&w.z));
        float2 q3 = __half22float2(*reinterpret_cast<__half2*>(&w.w));
        a0 += q0.x; a1 += q0.y; a2 += q1.x; a3 += q1.y;
        a4 += q2.x; a5 += q2.y; a6 += q3.x; a7 += q3.y;
    }
    float* outp = &g_bufa[v * 64 + ql * 8];
    *reinterpret_cast<float4*>(outp)     = make_float4(a0, a1, a2, a3);
    *reinterpret_cast<float4*>(outp + 4) = make_float4(a4, a5, a6, a7);
}

// shared FFMA2 GEMM mainloop + fp16 epilogue: dst[v] = half(dinv_v * (Z[v] @ W))
__device__ __forceinline__ void gemm_epi_h(const float2* Zs2, const float* __restrict__ W,
                                           __half2* __restrict__ dst,
                                           int base, int n, int tid) {
    int fg = tid & 15, ng = tid >> 4;
    int n0 = ng * 4;
    unsigned long long acc[4][2] = {};
    const unsigned long long* Wq = reinterpret_cast<const unsigned long long*>(W);
    #pragma unroll 4
    for (int k = 0; k < 64; k++) {
        unsigned long long w01 = __ldg(&Wq[k * 32 + fg * 2]);
        unsigned long long w23 = __ldg(&Wq[k * 32 + fg * 2 + 1]);
        #pragma unroll
        for (int j = 0; j < 4; j++) {
            unsigned long long z =
                *reinterpret_cast<const unsigned long long*>(&Zs2[(n0 + j) * 64 + k]);
            acc[j][0] = ffma2(z, w01, acc[j][0]);
            acc[j][1] = ffma2(z, w23, acc[j][1]);
        }
    }
    #pragma unroll
    for (int j = 0; j < 4; j++) {
        int v = base + n0 + j;
        if (v < n) {
            float dv = g_dinv[v];
            float2 a0 = *reinterpret_cast<float2*>(&acc[j][0]);
            float2 a1 = *reinterpret_cast<float2*>(&acc[j][1]);
            __half2 h0 = __floats2half2_rn(dv * a0.x, dv * a0.y);
            __half2 h1 = __floats2half2_rn(dv * a1.x, dv * a1.y);
            uint2 u;
            u.x = *reinterpret_cast<unsigned*>(&h0);
            u.y = *reinterpret_cast<unsigned*>(&h1);
            *reinterpret_cast<uint2*>(&dst[v * 32 + fg * 2]) = u;
        }
    }
}

// layer 1: z = relu(dinv*(agg9 @ W1) + b1); bufh = half(dinv * (z @ W2))
__global__ __launch_bounds__(256) void k_l1(const float* __restrict__ W1,
                                            const float* __restrict__ b1,
                                            const float* __restrict__ W2, int n) {
    __shared__ float W1s[9 * 64];
    __shared__ float A9s[64 * 9];
    __shared__ float dvs[64];
    __shared__ float b1s[64];
    __shared__ float2 Zs2[64 * 64];
    int tid = threadIdx.x;
    int base = blockIdx.x * 64;
    for (int i = tid; i < 576; i += 256) W1s[i] = W1[i];
    if (tid < 64) {
        int v = base + tid;
        dvs[tid] = (v < n) ? g_dinv[v] : 0.f;
        b1s[tid] = b1[tid];
    }
    for (int i = tid; i < 576; i += 256) {
        int nl = i / 9, k = i - nl * 9;
        int v = base + nl;
        A9s[i] = (v < n) ? g_agg9[v * 9 + k] : 0.f;
    }
    __syncthreads();
    for (int i = tid; i < 4096; i += 256) {
        int nl = i >> 6, f = i & 63;
        float s = 0.f;
        #pragma unroll
        for (int k = 0; k < 9; k++) s = fmaf(A9s[nl * 9 + k], W1s[k * 64 + f], s);
        float z = fmaxf(fmaf(dvs[nl], s, b1s[f]), 0.f);
        Zs2[nl * 64 + f] = make_float2(z, z);
    }
    __syncthreads();
    gemm_epi_h(Zs2, W2, g_bufh, base, n, tid);
}

// middle layer: z = relu(dinv*bufa + bias); bufh = half(dinv * (z @ W))
__global__ __launch_bounds__(256) void k_tf(const float* __restrict__ W,
                                            const float* __restrict__ bias, int n) {
    __shared__ float2 Zs2[64 * 64];
    __shared__ float b_s[64];
    __shared__ float dvs[64];
    int tid = threadIdx.x;
    int base = blockIdx.x * 64;
    if (tid < 64) {
        b_s[tid] = bias[tid];
        int v = base + tid;
        dvs[tid] = (v < n) ? g_dinv[v] : 0.f;
    }
    __syncthreads();
    for (int i = tid; i < 4096; i += 256) {
        int nl = i >> 6, f = i & 63;
        int v = base + nl;
        float z = 0.f;
        if (v < n) z = fmaxf(fmaf(dvs[nl], g_bufa[v * 64 + f], b_s[f]), 0.f);
        Zs2[nl * 64 + f] = make_float2(z, z);
    }
    __syncthreads();
    gemm_epi_h(Zs2, W, g_bufh, base, n, tid);
}

// pooling + head: 512 threads per graph (8 partials stride the nodes)
__global__ __launch_bounds__(512) void k_pool(const float* __restrict__ b3,
                                              const float* __restrict__ Wl,
                                              const float* __restrict__ bl,
                                              float* __restrict__ outp) {
    __shared__ float ssum[8][64];
    __shared__ float smax[8][64];
    __shared__ float pooled[128];
    int g = blockIdx.x, tid = threadIdx.x;
    int f = tid & 63, part = tid >> 6;
    int beg = g_goff[g], cnt = g_gcnt[g];
    float bf = b3[f];
    float sum = 0.f, mx = 0.f;   // relu>=0 -> 0 valid for max identity
    for (int i = part; i < cnt; i += 8) {
        int v = beg + i;
        float val = fmaxf(fmaf(g_dinv[v], g_bufa[v * 64 + f], bf), 0.f);
        sum += val;
        mx = fmaxf(mx, val);
    }
    ssum[part][f] = sum;
    smax[part][f] = mx;
    __syncthreads();
    if (tid < 64) {
        float s = 0.f, m = 0.f;
        #pragma unroll
        for (int w = 0; w < 8; w++) {
            s += ssum[w][tid];
            m = fmaxf(m, smax[w][tid]);
        }
        pooled[tid] = s / fmaxf((float)cnt, 1.f);
        pooled[64 + tid] = m;
    }
    __syncthreads();
    if (tid < 64) {
        float o = bl[tid];
        #pragma unroll 8
        for (int k = 0; k < 128; k++) o = fmaf(pooled[k], Wl[k * 64 + tid], o);
        outp[g * 64 + tid] = o;
    }
}

// -------------------- launcher --------------------

extern "C" void kernel_launch(void* const* d_in, const int* in_sizes, int n_in,
                              void* d_out, int out_size) {
    const float* x     = (const float*)d_in[0];
    const int*   ei    = (const int*)  d_in[1];
    const int*   batch = (const int*)  d_in[3];
    const float* W1    = (const float*)d_in[4];
    const float* b1    = (const float*)d_in[5];
    const float* W2    = (const float*)d_in[6];
    const float* b2    = (const float*)d_in[7];
    const float* W3    = (const float*)d_in[8];
    const float* b3    = (const float*)d_in[9];
    const float* Wl    = (const float*)d_in[10];
    const float* bl    = (const float*)d_in[11];
    float* out = (float*)d_out;

    int n = in_sizes[0] / 9;
    int e = in_sizes[1] / 2;
    const int* src = ei;
    const int* dst = ei + e;

    int gn  = (n + 255) / 256;
    int nb  = (n + 1023) / 1024;
    int ge4 = (e / 4 + 255) / 256 + 1;
    int gw2 = ((n + 1) / 2 * 32 + 255) / 256;   // 2 nodes per warp
    int gw4 = ((n + 3) / 4 * 32 + 255) / 256;   // 4 nodes per warp

    // graph structure
    k_zero<<<gn, 256>>>(n);
    k_count<<<ge4, 256>>>(dst, batch, n, e);
    k_scanA<<<nb, 1024>>>(n);
    k_scanB<<<1, 1024>>>(nb, n);
    k_scanC<<<gn, 256>>>(x, n);
    k_fill<<<ge4, 256>>>(src, dst, e);
    k_gscan<<<1, GMAX>>>();

    // layer 1
    k_gather9<<<gw2, 256>>>(n);
    k_l1<<<(n + 63) / 64, 256>>>(W1, b1, W2, n);
    // layer 2
    k_gather_h<<<gw4, 256>>>(n);
    k_tf<<<(n + 63) / 64, 256>>>(W3, b2, n);
    // layer 3
    k_gather_h<<<gw4, 256>>>(n);
    // pooling + head
    k_pool<<<GMAX, 512>>>(b3, Wl, bl, out);
}

// round 6
// speedup vs baseline: 1.2732x; 1.0482x over previous
#include <cuda_runtime.h>
#include <cuda_fp16.h>

#define NMAX 200000
#define EMAX 3200000
#define GMAX 1024

// ---- scratch (static device globals; no runtime allocation) ----
__device__ int     g_cnt[NMAX];
__device__ int     g_rowptr[NMAX + 1];
__device__ int     g_rank[EMAX];       // edge rank within its dst row
__device__ int     g_csr[EMAX];
__device__ int     g_bsums[1024];
__device__ int     g_gcnt[GMAX];
__device__ int     g_goff[GMAX];
__device__ float   g_dinv[NMAX];
__device__ __half2 g_xsh[NMAX * 8];    // layer-1 messages: 16 halves/row (9 real), 32B aligned
__device__ float   g_agg[NMAX * 16];   // layer-1 aggregated sums (padded to 16)
__device__ __half2 g_bufh[NMAX * 32];  // fp16 messages (layers 2/3)
__device__ float   g_bufa[NMAX * 64];  // fp32 aggregated sums

// packed fp32x2 FMA (FFMA2 — only reachable via PTX fma.rn.f32x2)
__device__ __forceinline__ unsigned long long ffma2(unsigned long long a,
                                                    unsigned long long b,
                                                    unsigned long long c) {
    unsigned long long d;
    asm("fma.rn.f32x2 %0, %1, %2, %3;" : "=l"(d) : "l"(a), "l"(b), "l"(c));
    return d;
}

// -------------------- setup kernels --------------------

__global__ void k_zero(int n) {
    int i = blockIdx.x * blockDim.x + threadIdx.x;
    if (i < n) g_cnt[i] = 0;
    if (i < GMAX) g_gcnt[i] = 0;
}

// 4 edges per thread; atomic returns rank within row (stored for rank-based fill)
__global__ void k_count(const int* __restrict__ dst, const int* __restrict__ batch,
                        int n, int e) {
    int i = blockIdx.x * blockDim.x + threadIdx.x;
    int e4 = i * 4;
    if (e4 + 4 <= e) {
        int4 d = *reinterpret_cast<const int4*>(&dst[e4]);
        int4 r;
        r.x = atomicAdd(&g_cnt[d.x], 1);
        r.y = atomicAdd(&g_cnt[d.y], 1);
        r.z = atomicAdd(&g_cnt[d.z], 1);
        r.w = atomicAdd(&g_cnt[d.w], 1);
        *reinterpret_cast<int4*>(&g_rank[e4]) = r;
    } else {
        for (int q = e4; q < e; q++) g_rank[q] = atomicAdd(&g_cnt[dst[q]], 1);
    }
    int n4 = i * 4;
    if (n4 + 4 <= n) {
        int4 b = *reinterpret_cast<const int4*>(&batch[n4]);
        atomicAdd(&g_gcnt[b.x], 1);
        atomicAdd(&g_gcnt[b.y], 1);
        atomicAdd(&g_gcnt[b.z], 1);
        atomicAdd(&g_gcnt[b.w], 1);
    } else {
        for (int q = n4; q < n; q++) atomicAdd(&g_gcnt[batch[q]], 1);
    }
}

// per-1024-block scan of cnt; extra last block (blockIdx == nb) performs the graph scan
__global__ void k_scanA(int n, int nb) {
    __shared__ int s[1024];
    int t = threadIdx.x;
    if ((int)blockIdx.x == nb) {   // graph-offset scan (needs only g_gcnt, ready after count)
        int v = g_gcnt[t];
        s[t] = v;
        __syncthreads();
        #pragma unroll
        for (int off = 1; off < 1024; off <<= 1) {
            int u = (t >= off) ? s[t - off] : 0;
            __syncthreads();
            s[t] += u;
            __syncthreads();
        }
        g_goff[t] = s[t] - v;
        return;
    }
    int i = blockIdx.x * 1024 + t;
    int v = (i < n) ? g_cnt[i] : 0;
    s[t] = v;
    __syncthreads();
    #pragma unroll
    for (int off = 1; off < 1024; off <<= 1) {
        int u = (t >= off) ? s[t - off] : 0;
        __syncthreads();
        s[t] += u;
        __syncthreads();
    }
    if (i < n) g_rowptr[i] = s[t] - v;
    if (t == 1023) g_bsums[blockIdx.x] = s[1023];
}

// fused: scan block sums in-block (nb <= 256), finalize rowptr, dinv, fp16 xs messages
__global__ void k_scanC(const float* __restrict__ x, int n, int nb) {
    __shared__ int sb[256];
    __shared__ int sbx[256];
    int t = threadIdx.x;
    int bv = (t < nb) ? g_bsums[t] : 0;
    sb[t] = bv;
    __syncthreads();
    #pragma unroll
    for (int off = 1; off < 256; off <<= 1) {
        int u = (t >= off) ? sb[t - off] : 0;
        __syncthreads();
        sb[t] += u;
        __syncthreads();
    }
    sbx[t] = sb[t] - bv;  // exclusive
    __syncthreads();
    int i = blockIdx.x * 256 + t;
    if (i < n) {
        g_rowptr[i] += sbx[i >> 10];
        float dv = rsqrtf((float)(g_cnt[i] + 1));
        g_dinv[i] = dv;
        __half2 h[8];
        #pragma unroll
        for (int k = 0; k < 8; k++) {
            float f0 = (2 * k     < 9) ? dv * x[i * 9 + 2 * k]     : 0.f;
            float f1 = (2 * k + 1 < 9) ? dv * x[i * 9 + 2 * k + 1] : 0.f;
            h[k] = __floats2half2_rn(f0, f1);
        }
        *reinterpret_cast<uint4*>(&g_xsh[i * 8])     = *reinterpret_cast<uint4*>(&h[0]);
        *reinterpret_cast<uint4*>(&g_xsh[i * 8 + 4]) = *reinterpret_cast<uint4*>(&h[4]);
    }
    if (blockIdx.x == 0 && t == 0) g_rowptr[n] = sb[255];  // grand total
}

// rank-based fill: no atomics
__global__ void k_fill(const int* __restrict__ src, const int* __restrict__ dst, int e) {
    int i = blockIdx.x * blockDim.x + threadIdx.x;
    int e4 = i * 4;
    if (e4 + 4 <= e) {
        int4 d = *reinterpret_cast<const int4*>(&dst[e4]);
        int4 s = *reinterpret_cast<const int4*>(&src[e4]);
        int4 r = *reinterpret_cast<const int4*>(&g_rank[e4]);
        g_csr[__ldg(&g_rowptr[d.x]) + r.x] = s.x;
        g_csr[__ldg(&g_rowptr[d.y]) + r.y] = s.y;
        g_csr[__ldg(&g_rowptr[d.z]) + r.z] = s.z;
        g_csr[__ldg(&g_rowptr[d.w]) + r.w] = s.w;
    } else {
        for (int q = e4; q < e; q++)
            g_csr[__ldg(&g_rowptr[dst[q]]) + g_rank[q]] = src[q];
    }
}

// -------------------- layer kernels --------------------

// layer-1 fp16 aggregation: 4 nodes per warp; 8 lanes per node, lane covers 2 feats (half2)
__global__ __launch_bounds__(256) void k_gather9h(int n) {
    int gw = (blockIdx.x * blockDim.x + threadIdx.x) >> 5;
    int lane = threadIdx.x & 31;
    int grp = lane >> 3, gl = lane & 7;
    int v = gw * 4 + grp;
    if (v >= n) return;
    int beg = g_rowptr[v], end = g_rowptr[v + 1];
    float2 p = __half22float2(__ldg(&g_xsh[v * 8 + gl]));   // self-loop
    float ax = p.x, ay = p.y;
    int e = beg;
    for (; e + 8 <= end; e += 8) {
        int s[8];
        #pragma unroll
        for (int q = 0; q < 8; q++) s[q] = __ldg(&g_csr[e + q]);
        #pragma unroll
        for (int q = 0; q < 8; q++) {
            float2 w = __half22float2(__ldg(&g_xsh[s[q] * 8 + gl]));
            ax += w.x; ay += w.y;
        }
    }
    for (; e < end; e++) {
        int s = __ldg(&g_csr[e]);
        float2 w = __half22float2(__ldg(&g_xsh[s * 8 + gl]));
        ax += w.x; ay += w.y;
    }
    *reinterpret_cast<float2*>(&g_agg[v * 16 + gl * 2]) = make_float2(ax, ay);
}

// fp16 aggregation: 4 nodes per warp; 8 lanes per node, each lane covers 8 feats (uint4)
__global__ __launch_bounds__(256) void k_gather_h(int n) {
    int gw = (blockIdx.x * blockDim.x + threadIdx.x) >> 5;
    int lane = threadIdx.x & 31;
    int quad = lane >> 3, ql = lane & 7;
    int v = gw * 4 + quad;
    if (v >= n) return;
    int beg = g_rowptr[v], end = g_rowptr[v + 1];
    const uint4* buf = reinterpret_cast<const uint4*>(g_bufh);
    uint4 u = __ldg(&buf[v * 8 + ql]);   // self-loop
    float2 p0 = __half22float2(*reinterpret_cast<__half2*>(&u.x));
    float2 p1 = __half22float2(*reinterpret_cast<__half2*>(&u.y));
    float2 p2 = __half22float2(*reinterpret_cast<__half2*>(&u.z));
    float2 p3 = __half22float2(*reinterpret_cast<__half2*>(&u.w));
    float a0 = p0.x, a1 = p0.y, a2 = p1.x, a3 = p1.y;
    float a4 = p2.x, a5 = p2.y, a6 = p3.x, a7 = p3.y;
    int e = beg;
    for (; e + 8 <= end; e += 8) {
        int s[8];
        #pragma unroll
        for (int q = 0; q < 8; q++) s[q] = __ldg(&g_csr[e + q]);
        #pragma unroll
        for (int q = 0; q < 8; q++) {
            uint4 w = __ldg(&buf[s[q] * 8 + ql]);
            float2 q0 = __half22float2(*reinterpret_cast<__half2*>(&w.x));
            float2 q1 = __half22float2(*reinterpret_cast<__half2*>(&w.y));
            float2 q2 = __half22float2(*reinterpret_cast<__half2*>(&w.z));
            float2 q3 = __half22float2(*reinterpret_cast<__half2*>(&w.w));
            a0 += q0.x; a1 += q0.y; a2 += q1.x; a3 += q1.y;
            a4 += q2.x; a5 += q2.y; a6 += q3.x; a7 += q3.y;
        }
    }
    for (; e < end; e++) {
        int s = __ldg(&g_csr[e]);
        uint4 w = __ldg(&buf[s * 8 + ql]);
        float2 q0 = __half22float2(*reinterpret_cast<__half2*>(&w.x));
        float2 q1 = __half22float2(*reinterpret_cast<__half2*>(&w.y));
        float2 q2 = __half22float2(*reinterpret_cast<__half2*>(&w.z));
        float2 q3 = __half22float2(*reinterpret_cast<__half2*>(&w.w));
        a0 += q0.x; a1 += q0.y; a2 += q1.x; a3 += q1.y;
        a4 += q2.x; a5 += q2.y; a6 += q3.x; a7 += q3.y;
    }
    float* outp = &g_bufa[v * 64 + ql * 8];
    *reinterpret_cast<float4*>(outp)     = make_float4(a0, a1, a2, a3);
    *reinterpret_cast<float4*>(outp + 4) = make_float4(a4, a5, a6, a7);
}

// shared FFMA2 GEMM mainloop + fp16 epilogue: dst[v] = half(dinv_v * (Z[v] @ W))
__device__ __forceinline__ void gemm_epi_h(const float2* Zs2, const float* __restrict__ W,
                                           __half2* __restrict__ dst,
                                           int base, int n, int tid) {
    int fg = tid & 15, ng = tid >> 4;
    int n0 = ng * 4;
    unsigned long long acc[4][2] = {};
    const unsigned long long* Wq = reinterpret_cast<const unsigned long long*>(W);
    #pragma unroll 4
    for (int k = 0; k < 64; k++) {
        unsigned long long w01 = __ldg(&Wq[k * 32 + fg * 2]);
        unsigned long long w23 = __ldg(&Wq[k * 32 + fg * 2 + 1]);
        #pragma unroll
        for (int j = 0; j < 4; j++) {
            unsigned long long z =
                *reinterpret_cast<const unsigned long long*>(&Zs2[(n0 + j) * 64 + k]);
            acc[j][0] = ffma2(z, w01, acc[j][0]);
            acc[j][1] = ffma2(z, w23, acc[j][1]);
        }
    }
    #pragma unroll
    for (int j = 0; j < 4; j++) {
        int v = base + n0 + j;
        if (v < n) {
            float dv = g_dinv[v];
            float2 a0 = *reinterpret_cast<float2*>(&acc[j][0]);
            float2 a1 = *reinterpret_cast<float2*>(&acc[j][1]);
            __half2 h0 = __floats2half2_rn(dv * a0.x, dv * a0.y);
            __half2 h1 = __floats2half2_rn(dv * a1.x, dv * a1.y);
            uint2 u;
            u.x = *reinterpret_cast<unsigned*>(&h0);
            u.y = *reinterpret_cast<unsigned*>(&h1);
            *reinterpret_cast<uint2*>(&dst[v * 32 + fg * 2]) = u;
        }
    }
}

// layer 1: z = relu(dinv*(agg @ W1) + b1); bufh = half(dinv * (z @ W2))
__global__ __launch_bounds__(256) void k_l1(const float* __restrict__ W1,
                                            const float* __restrict__ b1,
                                            const float* __restrict__ W2, int n) {
    __shared__ float W1s[9 * 64];
    __shared__ float A9s[64 * 16];
    __shared__ float dvs[64];
    __shared__ float b1s[64];
    __shared__ float2 Zs2[64 * 64];
    int tid = threadIdx.x;
    int base = blockIdx.x * 64;
    for (int i = tid; i < 576; i += 256) W1s[i] = W1[i];
    if (tid < 64) {
        int v = base + tid;
        dvs[tid] = (v < n) ? g_dinv[v] : 0.f;
        b1s[tid] = b1[tid];
    }
    for (int i = tid; i < 1024; i += 256) {
        int nl = i >> 4, k = i & 15;
        int v = base + nl;
        A9s[i] = (v < n) ? g_agg[v * 16 + k] : 0.f;
    }
    __syncthreads();
    for (int i = tid; i < 4096; i += 256) {
        int nl = i >> 6, f = i & 63;
        float s = 0.f;
        #pragma unroll
        for (int k = 0; k < 9; k++) s = fmaf(A9s[nl * 16 + k], W1s[k * 64 + f], s);
        float z = fmaxf(fmaf(dvs[nl], s, b1s[f]), 0.f);
        Zs2[nl * 64 + f] = make_float2(z, z);
    }
    __syncthreads();
    gemm_epi_h(Zs2, W2, g_bufh, base, n, tid);
}

// middle layer: z = relu(dinv*bufa + bias); bufh = half(dinv * (z @ W))
__global__ __launch_bounds__(256) void k_tf(const float* __restrict__ W,
                                            const float* __restrict__ bias, int n) {
    __shared__ float2 Zs2[64 * 64];
    __shared__ float b_s[64];
    __shared__ float dvs[64];
    int tid = threadIdx.x;
    int base = blockIdx.x * 64;
    if (tid < 64) {
        b_s[tid] = bias[tid];
        int v = base + tid;
        dvs[tid] = (v < n) ? g_dinv[v] : 0.f;
    }
    __syncthreads();
    for (int i = tid; i < 4096; i += 256) {
        int nl = i >> 6, f = i & 63;
        int v = base + nl;
        float z = 0.f;
        if (v < n) z = fmaxf(fmaf(dvs[nl], g_bufa[v * 64 + f], b_s[f]), 0.f);
        Zs2[nl * 64 + f] = make_float2(z, z);
    }
    __syncthreads();
    gemm_epi_h(Zs2, W, g_bufh, base, n, tid);
}

// pooling + head: 1024 threads per graph (16 partials stride the nodes)
__global__ __launch_bounds__(1024) void k_pool(const float* __restrict__ b3,
                                               const float* __restrict__ Wl,
                                               const float* __restrict__ bl,
                                               float* __restrict__ outp) {
    __shared__ float ssum[16][64];
    __shared__ float smax[16][64];
    __shared__ float pooled[128];
    int g = blockIdx.x, tid = threadIdx.x;
    int f = tid & 63, part = tid >> 6;
    int beg = g_goff[g], cnt = g_gcnt[g];
    float bf = b3[f];
    float sum = 0.f, mx = 0.f;   // relu>=0 -> 0 valid for max identity
    for (int i = part; i < cnt; i += 16) {
        int v = beg + i;
        float val = fmaxf(fmaf(g_dinv[v], g_bufa[v * 64 + f], bf), 0.f);
        sum += val;
        mx = fmaxf(mx, val);
    }
    ssum[part][f] = sum;
    smax[part][f] = mx;
    __syncthreads();
    if (tid < 64) {
        float s = 0.f, m = 0.f;
        #pragma unroll
        for (int w = 0; w < 16; w++) {
            s += ssum[w][tid];
            m = fmaxf(m, smax[w][tid]);
        }
        pooled[tid] = s / fmaxf((float)cnt, 1.f);
        pooled[64 + tid] = m;
    }
    __syncthreads();
    if (tid < 64) {
        float o = bl[tid];
        #pragma unroll 8
        for (int k = 0; k < 128; k++) o = fmaf(pooled[k], Wl[k * 64 + tid], o);
        outp[g * 64 + tid] = o;
    }
}

// -------------------- launcher --------------------

extern "C" void kernel_launch(void* const* d_in, const int* in_sizes, int n_in,
                              void* d_out, int out_size) {
    const float* x     = (const float*)d_in[0];
    const int*   ei    = (const int*)  d_in[1];
    const int*   batch = (const int*)  d_in[3];
    const float* W1    = (const float*)d_in[4];
    const float* b1    = (const float*)d_in[5];
    const float* W2    = (const float*)d_in[6];
    const float* b2    = (const float*)d_in[7];
    const float* W3    = (const float*)d_in[8];
    const float* b3    = (const float*)d_in[9];
    const float* Wl    = (const float*)d_in[10];
    const float* bl    = (const float*)d_in[11];
    float* out = (float*)d_out;

    int n = in_sizes[0] / 9;
    int e = in_sizes[1] / 2;
    const int* src = ei;
    const int* dst = ei + e;

    int gn  = (n + 255) / 256;
    int nb  = (n + 1023) / 1024;
    int ge4 = (e / 4 + 255) / 256 + 1;
    int gw4 = ((n + 3) / 4 * 32 + 255) / 256;   // 4 nodes per warp

    // graph structure (6 launches)
    k_zero<<<gn, 256>>>(n);
    k_count<<<ge4, 256>>>(dst, batch, n, e);
    k_scanA<<<nb + 1, 1024>>>(n, nb);        // extra block does graph-offset scan
    k_scanC<<<gn, 256>>>(x, n, nb);          // fused block-sum scan + finalize + fp16 xs
    k_fill<<<ge4, 256>>>(src, dst, e);

    // layer 1
    k_gather9h<<<gw4, 256>>>(n);
    k_l1<<<(n + 63) / 64, 256>>>(W1, b1, W2, n);
    // layer 2
    k_gather_h<<<gw4, 256>>>(n);
    k_tf<<<(n + 63) / 64, 256>>>(W3, b2, n);
    // layer 3
    k_gather_h<<<gw4, 256>>>(n);
    // pooling + head
    k_pool<<<GMAX, 1024>>>(b3, Wl, bl, out);
}

// round 7
// speedup vs baseline: 1.8071x; 1.4193x over previous
#include <cuda_runtime.h>
#include <cuda_fp16.h>

#define NMAX 200000
#define EMAX 3200000
#define GMAX 1024

// ---- scratch (static device globals; no runtime allocation) ----
__device__ int     g_cnt[NMAX];
__device__ int     g_rowptr[NMAX + 1];
__device__ int     g_rank[EMAX];
__device__ int     g_csr[EMAX];
__device__ int     g_bsums[1024];
__device__ int     g_gcnt[GMAX];
__device__ int     g_goff[GMAX];
__device__ float   g_dinv[NMAX];
__device__ __half2 g_xsh[NMAX * 8];    // layer-1 messages: 16 halves/row (9 real)
__device__ float   g_agg[NMAX * 16];   // layer-1 aggregated sums (fp32)
__device__ __half2 g_bufh[NMAX * 32];  // fp16 messages
__device__ __half2 g_zh[NMAX * 32];    // fp16 post-activation z (and final h3)

// -------------------- mma helpers --------------------

__device__ __forceinline__ void ldsm_x4(unsigned& a0, unsigned& a1, unsigned& a2,
                                        unsigned& a3, unsigned addr) {
    asm volatile("ldmatrix.sync.aligned.m8n8.x4.shared.b16 {%0,%1,%2,%3}, [%4];"
                 : "=r"(a0), "=r"(a1), "=r"(a2), "=r"(a3) : "r"(addr));
}
__device__ __forceinline__ void ldsm_x2_t(unsigned& b0, unsigned& b1, unsigned addr) {
    asm volatile("ldmatrix.sync.aligned.m8n8.x2.trans.shared.b16 {%0,%1}, [%2];"
                 : "=r"(b0), "=r"(b1) : "r"(addr));
}
__device__ __forceinline__ void mma_16816(float* c, unsigned a0, unsigned a1,
                                          unsigned a2, unsigned a3,
                                          unsigned b0, unsigned b1) {
    asm volatile("mma.sync.aligned.m16n8k16.row.col.f32.f16.f16.f32 "
                 "{%0,%1,%2,%3}, {%4,%5,%6,%7}, {%8,%9}, {%0,%1,%2,%3};"
                 : "+f"(c[0]), "+f"(c[1]), "+f"(c[2]), "+f"(c[3])
                 : "r"(a0), "r"(a1), "r"(a2), "r"(a3), "r"(b0), "r"(b1));
}

// -------------------- setup kernels --------------------

__global__ void k_zero(int n) {
    int i = blockIdx.x * blockDim.x + threadIdx.x;
    if (i < n) g_cnt[i] = 0;
    if (i < GMAX) g_gcnt[i] = 0;
}

__global__ void k_count(const int* __restrict__ dst, const int* __restrict__ batch,
                        int n, int e) {
    int i = blockIdx.x * blockDim.x + threadIdx.x;
    int e4 = i * 4;
    if (e4 + 4 <= e) {
        int4 d = *reinterpret_cast<const int4*>(&dst[e4]);
        int4 r;
        r.x = atomicAdd(&g_cnt[d.x], 1);
        r.y = atomicAdd(&g_cnt[d.y], 1);
        r.z = atomicAdd(&g_cnt[d.z], 1);
        r.w = atomicAdd(&g_cnt[d.w], 1);
        *reinterpret_cast<int4*>(&g_rank[e4]) = r;
    } else {
        for (int q = e4; q < e; q++) g_rank[q] = atomicAdd(&g_cnt[dst[q]], 1);
    }
    int n4 = i * 4;
    if (n4 + 4 <= n) {
        int4 b = *reinterpret_cast<const int4*>(&batch[n4]);
        atomicAdd(&g_gcnt[b.x], 1);
        atomicAdd(&g_gcnt[b.y], 1);
        atomicAdd(&g_gcnt[b.z], 1);
        atomicAdd(&g_gcnt[b.w], 1);
    } else {
        for (int q = n4; q < n; q++) atomicAdd(&g_gcnt[batch[q]], 1);
    }
}

// per-1024-block scan of cnt; extra last block performs the graph-offset scan
__global__ void k_scanA(int n, int nb) {
    __shared__ int s[1024];
    int t = threadIdx.x;
    if ((int)blockIdx.x == nb) {
        int v = g_gcnt[t];
        s[t] = v;
        __syncthreads();
        #pragma unroll
        for (int off = 1; off < 1024; off <<= 1) {
            int u = (t >= off) ? s[t - off] : 0;
            __syncthreads();
            s[t] += u;
            __syncthreads();
        }
        g_goff[t] = s[t] - v;
        return;
    }
    int i = blockIdx.x * 1024 + t;
    int v = (i < n) ? g_cnt[i] : 0;
    s[t] = v;
    __syncthreads();
    #pragma unroll
    for (int off = 1; off < 1024; off <<= 1) {
        int u = (t >= off) ? s[t - off] : 0;
        __syncthreads();
        s[t] += u;
        __syncthreads();
    }
    if (i < n) g_rowptr[i] = s[t] - v;
    if (t == 1023) g_bsums[blockIdx.x] = s[1023];
}

// fused: scan block sums in-block, finalize rowptr, dinv, fp16 xs messages
__global__ void k_scanC(const float* __restrict__ x, int n, int nb) {
    __shared__ int sb[256];
    __shared__ int sbx[256];
    int t = threadIdx.x;
    int bv = (t < nb) ? g_bsums[t] : 0;
    sb[t] = bv;
    __syncthreads();
    #pragma unroll
    for (int off = 1; off < 256; off <<= 1) {
        int u = (t >= off) ? sb[t - off] : 0;
        __syncthreads();
        sb[t] += u;
        __syncthreads();
    }
    sbx[t] = sb[t] - bv;
    __syncthreads();
    int i = blockIdx.x * 256 + t;
    if (i < n) {
        g_rowptr[i] += sbx[i >> 10];
        float dv = rsqrtf((float)(g_cnt[i] + 1));
        g_dinv[i] = dv;
        __half2 h[8];
        #pragma unroll
        for (int k = 0; k < 8; k++) {
            float f0 = (2 * k     < 9) ? dv * x[i * 9 + 2 * k]     : 0.f;
            float f1 = (2 * k + 1 < 9) ? dv * x[i * 9 + 2 * k + 1] : 0.f;
            h[k] = __floats2half2_rn(f0, f1);
        }
        *reinterpret_cast<uint4*>(&g_xsh[i * 8])     = *reinterpret_cast<uint4*>(&h[0]);
        *reinterpret_cast<uint4*>(&g_xsh[i * 8 + 4]) = *reinterpret_cast<uint4*>(&h[4]);
    }
    if (blockIdx.x == 0 && t == 0) g_rowptr[n] = sb[255];
}

__global__ void k_fill(const int* __restrict__ src, const int* __restrict__ dst, int e) {
    int i = blockIdx.x * blockDim.x + threadIdx.x;
    int e4 = i * 4;
    if (e4 + 4 <= e) {
        int4 d = *reinterpret_cast<const int4*>(&dst[e4]);
        int4 s = *reinterpret_cast<const int4*>(&src[e4]);
        int4 r = *reinterpret_cast<const int4*>(&g_rank[e4]);
        g_csr[__ldg(&g_rowptr[d.x]) + r.x] = s.x;
        g_csr[__ldg(&g_rowptr[d.y]) + r.y] = s.y;
        g_csr[__ldg(&g_rowptr[d.z]) + r.z] = s.z;
        g_csr[__ldg(&g_rowptr[d.w]) + r.w] = s.w;
    } else {
        for (int q = e4; q < e; q++)
            g_csr[__ldg(&g_rowptr[dst[q]]) + g_rank[q]] = src[q];
    }
}

// -------------------- layer kernels --------------------

// layer-1 fp16 aggregation: 4 nodes per warp; 8 lanes per node (half2)
__global__ __launch_bounds__(256) void k_gather9h(int n) {
    int gw = (blockIdx.x * blockDim.x + threadIdx.x) >> 5;
    int lane = threadIdx.x & 31;
    int grp = lane >> 3, gl = lane & 7;
    int v = gw * 4 + grp;
    if (v >= n) return;
    int beg = g_rowptr[v], end = g_rowptr[v + 1];
    float2 p = __half22float2(__ldg(&g_xsh[v * 8 + gl]));
    float ax = p.x, ay = p.y;
    int e = beg;
    for (; e + 8 <= end; e += 8) {
        int s[8];
        #pragma unroll
        for (int q = 0; q < 8; q++) s[q] = __ldg(&g_csr[e + q]);
        #pragma unroll
        for (int q = 0; q < 8; q++) {
            float2 w = __half22float2(__ldg(&g_xsh[s[q] * 8 + gl]));
            ax += w.x; ay += w.y;
        }
    }
    for (; e < end; e++) {
        int s = __ldg(&g_csr[e]);
        float2 w = __half22float2(__ldg(&g_xsh[s * 8 + gl]));
        ax += w.x; ay += w.y;
    }
    *reinterpret_cast<float2*>(&g_agg[v * 16 + gl * 2]) = make_float2(ax, ay);
}

// fp16 gather + fused epilogue: z[v] = relu(dinv*(self+neighbors) + bias), fp16 out
// 4 nodes per warp; 8 lanes per node, each lane covers 8 feats (uint4)
__global__ __launch_bounds__(256) void k_gather_z(const float* __restrict__ bias, int n) {
    int gw = (blockIdx.x * blockDim.x + threadIdx.x) >> 5;
    int lane = threadIdx.x & 31;
    int quad = lane >> 3, ql = lane & 7;
    int v = gw * 4 + quad;
    if (v >= n) return;
    int beg = g_rowptr[v], end = g_rowptr[v + 1];
    const uint4* buf = reinterpret_cast<const uint4*>(g_bufh);
    uint4 u = __ldg(&buf[v * 8 + ql]);   // self-loop
    float2 p0 = __half22float2(*reinterpret_cast<__half2*>(&u.x));
    float2 p1 = __half22float2(*reinterpret_cast<__half2*>(&u.y));
    float2 p2 = __half22float2(*reinterpret_cast<__half2*>(&u.z));
    float2 p3 = __half22float2(*reinterpret_cast<__half2*>(&u.w));
    float a0 = p0.x, a1 = p0.y, a2 = p1.x, a3 = p1.y;
    float a4 = p2.x, a5 = p2.y, a6 = p3.x, a7 = p3.y;
    int e = beg;
    for (; e + 8 <= end; e += 8) {
        int s[8];
        #pragma unroll
        for (int q = 0; q < 8; q++) s[q] = __ldg(&g_csr[e + q]);
        #pragma unroll
        for (int q = 0; q < 8; q++) {
            uint4 w = __ldg(&buf[s[q] * 8 + ql]);
            float2 q0 = __half22float2(*reinterpret_cast<__half2*>(&w.x));
            float2 q1 = __half22float2(*reinterpret_cast<__half2*>(&w.y));
            float2 q2 = __half22float2(*reinterpret_cast<__half2*>(&w.z));
            float2 q3 = __half22float2(*reinterpret_cast<__half2*>(&w.w));
            a0 += q0.x; a1 += q0.y; a2 += q1.x; a3 += q1.y;
            a4 += q2.x; a5 += q2.y; a6 += q3.x; a7 += q3.y;
        }
    }
    for (; e < end; e++) {
        int s = __ldg(&g_csr[e]);
        uint4 w = __ldg(&buf[s * 8 + ql]);
        float2 q0 = __half22float2(*reinterpret_cast<__half2*>(&w.x));
        float2 q1 = __half22float2(*reinterpret_cast<__half2*>(&w.y));
        float2 q2 = __half22float2(*reinterpret_cast<__half2*>(&w.z));
        float2 q3 = __half22float2(*reinterpret_cast<__half2*>(&w.w));
        a0 += q0.x; a1 += q0.y; a2 += q1.x; a3 += q1.y;
        a4 += q2.x; a5 += q2.y; a6 += q3.x; a7 += q3.y;
    }
    // fused epilogue: z = relu(dinv*a + b) in fp16
    float dv = g_dinv[v];
    float4 b0 = __ldg(&reinterpret_cast<const float4*>(bias)[ql * 2]);
    float4 b1 = __ldg(&reinterpret_cast<const float4*>(bias)[ql * 2 + 1]);
    __half2 h[4];
    h[0] = __floats2half2_rn(fmaxf(fmaf(dv, a0, b0.x), 0.f), fmaxf(fmaf(dv, a1, b0.y), 0.f));
    h[1] = __floats2half2_rn(fmaxf(fmaf(dv, a2, b0.z), 0.f), fmaxf(fmaf(dv, a3, b0.w), 0.f));
    h[2] = __floats2half2_rn(fmaxf(fmaf(dv, a4, b1.x), 0.f), fmaxf(fmaf(dv, a5, b1.y), 0.f));
    h[3] = __floats2half2_rn(fmaxf(fmaf(dv, a6, b1.z), 0.f), fmaxf(fmaf(dv, a7, b1.w), 0.f));
    *reinterpret_cast<uint4*>(&g_zh[v * 32 + ql * 4]) = *reinterpret_cast<uint4*>(h);
}

// shared HMMA stage: out = Zs(fp16, 72-stride) @ Ws(fp16, 72-stride);
// messages dst[v] = half(dinv*out). 8 warps: 4 m-tiles x 2 n-tiles.
__device__ __forceinline__ void mma_stage(const __half* Zs, const __half* Ws,
                                          const float* dvs, int base, int n,
                                          int tid, __half2* __restrict__ dst) {
    int lane = tid & 31, wid = tid >> 5;
    int mt = wid & 3, nt = wid >> 2;
    float acc[4][4] = {};
    unsigned zbase = (unsigned)__cvta_generic_to_shared(Zs);
    unsigned wbase = (unsigned)__cvta_generic_to_shared(Ws);
    #pragma unroll
    for (int k = 0; k < 4; k++) {
        unsigned a0, a1, a2, a3;
        int arow = mt * 16 + (lane & 15);
        ldsm_x4(a0, a1, a2, a3, zbase + (arow * 72 + k * 16 + (lane >> 4) * 8) * 2);
        #pragma unroll
        for (int t = 0; t < 4; t++) {
            unsigned b0, b1;
            int brow = k * 16 + (lane & 15);
            ldsm_x2_t(b0, b1, wbase + (brow * 72 + nt * 32 + t * 8) * 2);
            mma_16816(acc[t], a0, a1, a2, a3, b0, b1);
        }
    }
    int r0 = mt * 16 + (lane >> 2), r1 = r0 + 8;
    int cp = lane & 3;
    float dv0 = dvs[r0], dv1 = dvs[r1];
    int v0 = base + r0, v1 = base + r1;
    #pragma unroll
    for (int t = 0; t < 4; t++) {
        int colpair = nt * 16 + t * 4 + cp;
        if (v0 < n)
            dst[v0 * 32 + colpair] = __floats2half2_rn(dv0 * acc[t][0], dv0 * acc[t][1]);
        if (v1 < n)
            dst[v1 * 32 + colpair] = __floats2half2_rn(dv1 * acc[t][2], dv1 * acc[t][3]);
    }
}

// layer 1: z1 = relu(dinv*(agg@W1)+b1) (fp32 FFMA, 9-dim); msgs = half(dinv*(z1@W2)) via HMMA
__global__ __launch_bounds__(256) void k_l1_mma(const float* __restrict__ W1,
                                                const float* __restrict__ b1,
                                                const float* __restrict__ W2, int n) {
    __shared__ float W1s[9 * 64];
    __shared__ float A9s[64 * 16];
    __shared__ float dvs[64];
    __shared__ float b1s[64];
    __shared__ __half Zs[64 * 72];
    __shared__ __half Ws[64 * 72];
    int tid = threadIdx.x;
    int base = blockIdx.x * 64;
    for (int i = tid; i < 576; i += 256) W1s[i] = W1[i];
    if (tid < 64) {
        int v = base + tid;
        dvs[tid] = (v < n) ? g_dinv[v] : 0.f;
        b1s[tid] = b1[tid];
    }
    for (int i = tid; i < 4096; i += 256) {
        int k = i >> 6, f = i & 63;
        Ws[k * 72 + f] = __float2half(W2[i]);
    }
    for (int i = tid; i < 1024; i += 256) {
        int nl = i >> 4, k = i & 15;
        int v = base + nl;
        A9s[i] = (v < n) ? g_agg[v * 16 + k] : 0.f;
    }
    __syncthreads();
    for (int i = tid; i < 4096; i += 256) {
        int nl = i >> 6, f = i & 63;
        float s = 0.f;
        #pragma unroll
        for (int k = 0; k < 9; k++) s = fmaf(A9s[nl * 16 + k], W1s[k * 64 + f], s);
        Zs[nl * 72 + f] = __float2half(fmaxf(fmaf(dvs[nl], s, b1s[f]), 0.f));
    }
    __syncthreads();
    mma_stage(Zs, Ws, dvs, base, n, tid, g_bufh);
}

// middle layer: msgs = half(dinv*(z@W)) via HMMA, z read fp16 from g_zh
__global__ __launch_bounds__(256) void k_tf_mma(const float* __restrict__ W, int n) {
    __shared__ __half Zs[64 * 72];
    __shared__ __half Ws[64 * 72];
    __shared__ float dvs[64];
    int tid = threadIdx.x;
    int base = blockIdx.x * 64;
    if (tid < 64) {
        int v = base + tid;
        dvs[tid] = (v < n) ? g_dinv[v] : 0.f;
    }
    for (int i = tid; i < 4096; i += 256) {
        int k = i >> 6, f = i & 63;
        Ws[k * 72 + f] = __float2half(W[i]);
    }
    for (int i = tid; i < 512; i += 256) {
        int r = i >> 3, q = i & 7;
        int v = base + r;
        uint4 val = (v < n) ? *reinterpret_cast<const uint4*>(&g_zh[v * 32 + q * 4])
                            : make_uint4(0, 0, 0, 0);
        *reinterpret_cast<uint4*>(&Zs[r * 72 + q * 8]) = val;
    }
    __syncthreads();
    mma_stage(Zs, Ws, dvs, base, n, tid, g_bufh);
}

// pooling + head: h3 fp16 in g_zh; 32 partials x 32 feat-pairs
__global__ __launch_bounds__(1024) void k_pool(const float* __restrict__ Wl,
                                               const float* __restrict__ bl,
                                               float* __restrict__ outp) {
    __shared__ float ssum[32][64];
    __shared__ float smax[32][64];
    __shared__ float pooled[128];
    int g = blockIdx.x, tid = threadIdx.x;
    int fp = tid & 31, part = tid >> 5;
    int beg = g_goff[g], cnt = g_gcnt[g];
    float sx = 0.f, sy = 0.f, mx = 0.f, my = 0.f;
    for (int i = part; i < cnt; i += 32) {
        int v = beg + i;
        float2 h = __half22float2(__ldg(&g_zh[v * 32 + fp]));
        sx += h.x; sy += h.y;
        mx = fmaxf(mx, h.x); my = fmaxf(my, h.y);
    }
    ssum[part][fp * 2] = sx; ssum[part][fp * 2 + 1] = sy;
    smax[part][fp * 2] = mx; smax[part][fp * 2 + 1] = my;
    __syncthreads();
    if (tid < 64) {
        float s = 0.f, m = 0.f;
        #pragma unroll
        for (int w = 0; w < 32; w++) {
            s += ssum[w][tid];
            m = fmaxf(m, smax[w][tid]);
        }
        pooled[tid] = s / fmaxf((float)cnt, 1.f);
        pooled[64 + tid] = m;
    }
    __syncthreads();
    if (tid < 64) {
        float o = bl[tid];
        #pragma unroll 8
        for (int k = 0; k < 128; k++) o = fmaf(pooled[k], Wl[k * 64 + tid], o);
        outp[g * 64 + tid] = o;
    }
}

// -------------------- launcher --------------------

extern "C" void kernel_launch(void* const* d_in, const int* in_sizes, int n_in,
                              void* d_out, int out_size) {
    const float* x     = (const float*)d_in[0];
    const int*   ei    = (const int*)  d_in[1];
    const int*   batch = (const int*)  d_in[3];
    const float* W1    = (const float*)d_in[4];
    const float* b1    = (const float*)d_in[5];
    const float* W2    = (const float*)d_in[6];
    const float* b2    = (const float*)d_in[7];
    const float* W3    = (const float*)d_in[8];
    const float* b3    = (const float*)d_in[9];
    const float* Wl    = (const float*)d_in[10];
    const float* bl    = (const float*)d_in[11];
    float* out = (float*)d_out;

    int n = in_sizes[0] / 9;
    int e = in_sizes[1] / 2;
    const int* src = ei;
    const int* dst = ei + e;

    int gn  = (n + 255) / 256;
    int nb  = (n + 1023) / 1024;
    int ge4 = (e / 4 + 255) / 256 + 1;
    int gw4 = ((n + 3) / 4 * 32 + 255) / 256;

    // graph structure
    k_zero<<<gn, 256>>>(n);
    k_count<<<ge4, 256>>>(dst, batch, n, e);
    k_scanA<<<nb + 1, 1024>>>(n, nb);
    k_scanC<<<gn, 256>>>(x, n, nb);
    k_fill<<<ge4, 256>>>(src, dst, e);

    // layer 1: 9-dim gather + (W1, relu, W2) transform -> messages
    k_gather9h<<<gw4, 256>>>(n);
    k_l1_mma<<<(n + 63) / 64, 256>>>(W1, b1, W2, n);
    // layer 2: gather + epilogue(b2) -> z2; z2@W3 -> messages
    k_gather_z<<<gw4, 256>>>(b2, n);
    k_tf_mma<<<(n + 63) / 64, 256>>>(W3, n);
    // layer 3: gather + epilogue(b3) -> h3
    k_gather_z<<<gw4, 256>>>(b3, n);
    // pooling + head
    k_pool<<<GMAX, 1024>>>(Wl, bl, out);
}